// round 15
// baseline (speedup 1.0000x reference)
#include <cuda_runtime.h>

// Problem constants (fixed by the dataset)
#define BATCH  4096
#define TT     1000
#define HID    32
#define HH     15    // padded to 16
#define OUTD   8
#define INITD  16

#define NTHR   128                    // threads per block
#define GPB    (NTHR / 8)             // 16 role-groups per block
#define EPB    (GPB * 2)              // 32 elements per block (ILP2)
#define NBLK   (BATCH / EPB)          // 128 blocks -> 512 warps, 1/SMSP

typedef unsigned long long u64;

__device__ __forceinline__ u64 pack2(float x, float y) {
    u64 r; asm("mov.b64 %0, {%1,%2};" : "=l"(r) : "f"(x), "f"(y)); return r;
}
__device__ __forceinline__ float2 unpack2(u64 v) {
    float2 p; asm("mov.b64 {%0,%1}, %2;" : "=f"(p.x), "=f"(p.y) : "l"(v)); return p;
}
// Packed f32x2 FMA / ADD (sm_100+; ptxas will not auto-fuse these)
__device__ __forceinline__ u64 fma2(u64 a, u64 b, u64 c) {
    u64 d; asm("fma.rn.f32x2 %0, %1, %2, %3;" : "=l"(d) : "l"(a), "l"(b), "l"(c)); return d;
}
__device__ __forceinline__ u64 add2(u64 a, u64 b) {
    u64 d; asm("add.rn.f32x2 %0, %1, %2;" : "=l"(d) : "l"(a), "l"(b)); return d;
}

// tanh(x) = 1 - 2/(e^{2x}+1).  e->inf gives 1, e->0 gives -1: no clamp needed.
__device__ __forceinline__ float ftanh(float x) {
    float e = __expf(2.f * x);
    return 1.f - __fdividef(2.f, e + 1.f);
}

// 16-input dot; weights and inputs both as 8 packed k-pairs held in registers.
__device__ __forceinline__ float dot16r(const u64 (&w)[8], const u64 (&v)[8],
                                        float bias) {
    u64 acc0 = pack2(bias, 0.f);
    u64 acc1 = pack2(0.f, 0.f);
#pragma unroll
    for (int p = 0; p < 4; p++) {
        acc0 = fma2(v[2 * p + 0], w[2 * p + 0], acc0);
        acc1 = fma2(v[2 * p + 1], w[2 * p + 1], acc1);
    }
    float2 s = unpack2(add2(acc0, acc1));
    return s.x + s.y;
}

__global__ void __launch_bounds__(NTHR) node_kernel(
    const float* __restrict__ times, const float* __restrict__ initial,
    const float* __restrict__ Wi,  const float* __restrict__ bi,
    const float* __restrict__ Wf0, const float* __restrict__ bf0,
    const float* __restrict__ Wf1, const float* __restrict__ bf1,
    const float* __restrict__ Wf2, const float* __restrict__ bf2,
    const float* __restrict__ Wf3, const float* __restrict__ bf3,
    const float* __restrict__ Wl,  const float* __restrict__ bl,
    float* __restrict__ out)
{
    // Transposed, zero-padded weight tiles (built once; the hot loop reads
    // NO shared memory except the sDt broadcast).
    __shared__ __align__(16) float sT1[16][16];   // Wf1^T  [j][k]
    __shared__ __align__(16) float sT2[16][16];   // Wf2^T  [j][k]
    __shared__ __align__(16) float sMt[16][16];   // M^T,   M = Wf3@Wf0   [15x15]
    __shared__ __align__(16) float sPt[8][16];    // P^T,   P = Wf3@Wl    [15x8]
    __shared__ __align__(16) float sWf0[32][16];  // Wf0    [c][j] padded
    __shared__ __align__(16) float sWi[INITD][HID];
    __shared__ __align__(16) float sWl[HID][OUTD];
    __shared__ float sB0[16], sB1[16], sB2[16], sC[16], sQ[OUTD], sBl[OUTD];
    __shared__ float sDt[TT - 1];

    const int tid = threadIdx.x;

    // ---- zero padded arrays ----
    for (int i = tid; i < 16 * 16; i += NTHR) {
        (&sT1[0][0])[i] = 0.f; (&sT2[0][0])[i] = 0.f; (&sMt[0][0])[i] = 0.f;
    }
    for (int i = tid; i < 8 * 16; i += NTHR)  (&sPt[0][0])[i]  = 0.f;
    for (int i = tid; i < 32 * 16; i += NTHR) (&sWf0[0][0])[i] = 0.f;
    if (tid < 16) { sB0[tid] = 0.f; sB1[tid] = 0.f; sB2[tid] = 0.f; sC[tid] = 0.f; }
    __syncthreads();

    // ---- fill transposed weights + fused operators ----
    for (int i = tid; i < HH * HH; i += NTHR) {       // Wf1/Wf2 [15][15]
        int k = i / HH, j = i % HH;
        sT1[j][k] = Wf1[i];
        sT2[j][k] = Wf2[i];
    }
    for (int i = tid; i < HID * HH; i += NTHR) {      // Wf0 [32][15]
        int c = i / HH, j = i % HH;
        sWf0[c][j] = Wf0[i];
    }
    for (int i = tid; i < INITD * HID; i += NTHR) (&sWi[0][0])[i] = Wi[i];
    for (int i = tid; i < HID * OUTD; i += NTHR)  (&sWl[0][0])[i] = Wl[i];

    // M = Wf3 @ Wf0 : M[k][j] = sum_m Wf3[k][m]*Wf0[m][j]   (stored transposed)
    for (int i = tid; i < HH * HH; i += NTHR) {
        int k = i / HH, j = i % HH;
        float acc = 0.f;
#pragma unroll
        for (int m = 0; m < HID; m++) acc = fmaf(Wf3[k * HID + m], Wf0[m * HH + j], acc);
        sMt[j][k] = acc;
    }
    // P = Wf3 @ Wl : P[k][o] = sum_m Wf3[k][m]*Wl[m][o]     (stored transposed)
    for (int i = tid; i < HH * OUTD; i += NTHR) {
        int k = i / OUTD, o = i % OUTD;
        float acc = 0.f;
#pragma unroll
        for (int m = 0; m < HID; m++) acc = fmaf(Wf3[k * HID + m], Wl[m * OUTD + o], acc);
        sPt[o][k] = acc;
    }
    // c = bf3 @ Wf0, q = bf3 @ Wl
    if (tid < HH) {
        float acc = 0.f;
#pragma unroll
        for (int m = 0; m < HID; m++) acc = fmaf(bf3[m], Wf0[m * HH + tid], acc);
        sC[tid] = acc;
    }
    if (tid < OUTD) {
        float acc = 0.f;
#pragma unroll
        for (int m = 0; m < HID; m++) acc = fmaf(bf3[m], Wl[m * OUTD + tid], acc);
        sQ[tid] = acc;
        sBl[tid] = bl[tid];
    }
    if (tid < HH) { sB0[tid] = bf0[tid]; sB1[tid] = bf1[tid]; sB2[tid] = bf2[tid]; }
    for (int t = tid; t < TT - 1; t += NTHR) sDt[t] = times[t + 1] - times[t];
    __syncthreads();

    // ---- mapping: 8 consecutive lanes = one role group; each group
    //      integrates TWO batch elements (ILP2) ----
    const int g  = tid >> 3;                    // group within block
    const int r  = tid & 7;                     // role 0..7
    const int e0 = blockIdx.x * EPB + 2 * g;
    const int e1 = e0 + 1;
    const unsigned FULL = 0xffffffffu;

    // ---- hoist this role's weights into registers (packed k-pairs);
    //      shared between both elements ----
    u64 w1e[8], w1o[8], w2e[8], w2o[8], wMe[8], wMo[8], wP[8];
#pragma unroll
    for (int p = 0; p < 8; p++) {
        w1e[p] = *(const u64*)&sT1[2 * r][2 * p];
        w1o[p] = *(const u64*)&sT1[2 * r + 1][2 * p];
        w2e[p] = *(const u64*)&sT2[2 * r][2 * p];
        w2o[p] = *(const u64*)&sT2[2 * r + 1][2 * p];
        wMe[p] = *(const u64*)&sMt[2 * r][2 * p];
        wMo[p] = *(const u64*)&sMt[2 * r + 1][2 * p];
        wP[p]  = *(const u64*)&sPt[r][2 * p];
    }
    const float b1e = sB1[2 * r], b1o = sB1[2 * r + 1];
    const float b2e = sB2[2 * r], b2o = sB2[2 * r + 1];
    const float cE  = sC[2 * r],  cO  = sC[2 * r + 1];
    const float qr  = sQ[r];

    // ---- initial state for one element: u pair + y scalar ----
    auto init_state = [&](int e, u64& up, float& yr) {
        float x[INITD];
#pragma unroll
        for (int k = 0; k < INITD; k++) x[k] = initial[e * INITD + k];
        float h0[HID];
#pragma unroll
        for (int c = 0; c < HID; c++) {
            float a = bi[c];
#pragma unroll
            for (int k = 0; k < INITD; k++) a = fmaf(x[k], sWi[k][c], a);
            h0[c] = a;
        }
        float ua = sB0[2 * r], ub = sB0[2 * r + 1];
        float y  = sBl[r];
#pragma unroll
        for (int c = 0; c < HID; c++) {
            ua = fmaf(h0[c], sWf0[c][2 * r],     ua);
            ub = fmaf(h0[c], sWf0[c][2 * r + 1], ub);
            y  = fmaf(h0[c], sWl[c][r],          y);
        }
        up = pack2(ua, ub);
        yr = y;
    };

    u64 up0, up1; float y0, y1;
    init_state(e0, up0, y0);
    init_state(e1, up1, y1);

    float* __restrict__ o0 = out + (size_t)e0 * TT * OUTD + r;
    float* __restrict__ o1 = out + (size_t)e1 * TT * OUTD + r;
    o0[0] = y0;
    o1[0] = y1;

    u64 zp0[8], zp1[8];
    for (int t = 0; t < TT - 1; t++) {
        const float dt = sDt[t];
        const u64 dt2 = pack2(dt, dt);

        // ---- z0 = tanh(u), gather across group (both elements) ----
        float2 uu0 = unpack2(up0);
        float2 uu1 = unpack2(up1);
        u64 pl0 = pack2(ftanh(uu0.x), ftanh(uu0.y));
        u64 pl1 = pack2(ftanh(uu1.x), ftanh(uu1.y));
#pragma unroll
        for (int j = 0; j < 8; j++) {
            zp0[j] = __shfl_sync(FULL, pl0, j, 8);
            zp1[j] = __shfl_sync(FULL, pl1, j, 8);
        }

        // ---- z1 = tanh(z0 @ Wf1 + b1) ----
        float a00 = ftanh(dot16r(w1e, zp0, b1e));
        float a01 = ftanh(dot16r(w1o, zp0, b1o));
        float a10 = ftanh(dot16r(w1e, zp1, b1e));
        float a11 = ftanh(dot16r(w1o, zp1, b1o));
        pl0 = pack2(a00, a01);
        pl1 = pack2(a10, a11);
#pragma unroll
        for (int j = 0; j < 8; j++) {
            zp0[j] = __shfl_sync(FULL, pl0, j, 8);
            zp1[j] = __shfl_sync(FULL, pl1, j, 8);
        }

        // ---- z2 = tanh(z1 @ Wf2 + b2) ----
        a00 = ftanh(dot16r(w2e, zp0, b2e));
        a01 = ftanh(dot16r(w2o, zp0, b2o));
        a10 = ftanh(dot16r(w2e, zp1, b2e));
        a11 = ftanh(dot16r(w2o, zp1, b2o));
        pl0 = pack2(a00, a01);
        pl1 = pack2(a10, a11);
#pragma unroll
        for (int j = 0; j < 8; j++) {
            zp0[j] = __shfl_sync(FULL, pl0, j, 8);
            zp1[j] = __shfl_sync(FULL, pl1, j, 8);
        }

        // ---- u += dt * (z2 @ M + c)  (local pair, no gather) ----
        float d00 = dot16r(wMe, zp0, cE);
        float d01 = dot16r(wMo, zp0, cO);
        float d10 = dot16r(wMe, zp1, cE);
        float d11 = dot16r(wMo, zp1, cO);
        up0 = fma2(pack2(d00, d01), dt2, up0);
        up1 = fma2(pack2(d10, d11), dt2, up1);

        // ---- y += dt * (z2 @ P + q), store ----
        float dy0 = dot16r(wP, zp0, qr);
        float dy1 = dot16r(wP, zp1, qr);
        y0 = fmaf(dt, dy0, y0);
        y1 = fmaf(dt, dy1, y1);
        o0[(size_t)(t + 1) * OUTD] = y0;
        o1[(size_t)(t + 1) * OUTD] = y1;
    }
}

extern "C" void kernel_launch(void* const* d_in, const int* in_sizes, int n_in,
                              void* d_out, int out_size) {
    const float* times   = (const float*)d_in[0];
    const float* initial = (const float*)d_in[1];
    const float* Wi  = (const float*)d_in[2];
    const float* bi  = (const float*)d_in[3];
    const float* Wf0 = (const float*)d_in[4];
    const float* bf0 = (const float*)d_in[5];
    const float* Wf1 = (const float*)d_in[6];
    const float* bf1 = (const float*)d_in[7];
    const float* Wf2 = (const float*)d_in[8];
    const float* bf2 = (const float*)d_in[9];
    const float* Wf3 = (const float*)d_in[10];
    const float* bf3 = (const float*)d_in[11];
    const float* Wl  = (const float*)d_in[12];
    const float* bl  = (const float*)d_in[13];
    float* out = (float*)d_out;

    node_kernel<<<NBLK, NTHR>>>(times, initial, Wi, bi,
                                Wf0, bf0, Wf1, bf1, Wf2, bf2, Wf3, bf3,
                                Wl, bl, out);
}

// round 16
// speedup vs baseline: 1.1363x; 1.1363x over previous
#include <cuda_runtime.h>

// Problem constants (fixed by the dataset)
#define BATCH  4096
#define TT     1000
#define HID    32
#define HH     15    // padded to 16
#define OUTD   8
#define INITD  16

// 8 threads per element. 256-thread blocks (8 warps) on a 128-block grid:
// every block owns one SM -> exactly 2 warps per SMSP, uniformly (no
// straggler SMs at 1 warp/SMSP, which set the pace in the 256x128 config).
#define NTHR   256
#define EPB    (NTHR / 8)             // 32 elements per block
#define NBLK   (BATCH / EPB)          // 128 blocks

typedef unsigned long long u64;

__device__ __forceinline__ u64 pack2(float x, float y) {
    u64 r; asm("mov.b64 %0, {%1,%2};" : "=l"(r) : "f"(x), "f"(y)); return r;
}
__device__ __forceinline__ float2 unpack2(u64 v) {
    float2 p; asm("mov.b64 {%0,%1}, %2;" : "=f"(p.x), "=f"(p.y) : "l"(v)); return p;
}
// Packed f32x2 FMA / ADD (sm_100+; ptxas will not auto-fuse these)
__device__ __forceinline__ u64 fma2(u64 a, u64 b, u64 c) {
    u64 d; asm("fma.rn.f32x2 %0, %1, %2, %3;" : "=l"(d) : "l"(a), "l"(b), "l"(c)); return d;
}
__device__ __forceinline__ u64 add2(u64 a, u64 b) {
    u64 d; asm("add.rn.f32x2 %0, %1, %2;" : "=l"(d) : "l"(a), "l"(b)); return d;
}

// tanh(x) = 1 - 2/(e^{2x}+1).  e->inf gives 1, e->0 gives -1: no clamp needed.
__device__ __forceinline__ float ftanh(float x) {
    float e = __expf(2.f * x);
    return 1.f - __fdividef(2.f, e + 1.f);
}

// 16-input dot; weights and inputs both as 8 packed k-pairs held in registers.
__device__ __forceinline__ float dot16r(const u64 (&w)[8], const u64 (&v)[8],
                                        float bias) {
    u64 acc0 = pack2(bias, 0.f);
    u64 acc1 = pack2(0.f, 0.f);
#pragma unroll
    for (int p = 0; p < 4; p++) {
        acc0 = fma2(v[2 * p + 0], w[2 * p + 0], acc0);
        acc1 = fma2(v[2 * p + 1], w[2 * p + 1], acc1);
    }
    float2 s = unpack2(add2(acc0, acc1));
    return s.x + s.y;
}

__global__ void __launch_bounds__(NTHR) node_kernel(
    const float* __restrict__ times, const float* __restrict__ initial,
    const float* __restrict__ Wi,  const float* __restrict__ bi,
    const float* __restrict__ Wf0, const float* __restrict__ bf0,
    const float* __restrict__ Wf1, const float* __restrict__ bf1,
    const float* __restrict__ Wf2, const float* __restrict__ bf2,
    const float* __restrict__ Wf3, const float* __restrict__ bf3,
    const float* __restrict__ Wl,  const float* __restrict__ bl,
    float* __restrict__ out)
{
    // Transposed, zero-padded weight tiles (built once; the hot loop reads
    // NO shared memory except the sDt broadcast).
    __shared__ __align__(16) float sT1[16][16];   // Wf1^T  [j][k]
    __shared__ __align__(16) float sT2[16][16];   // Wf2^T  [j][k]
    __shared__ __align__(16) float sMt[16][16];   // M^T,   M = Wf3@Wf0   [15x15]
    __shared__ __align__(16) float sPt[8][16];    // P^T,   P = Wf3@Wl    [15x8]
    __shared__ __align__(16) float sWf0[32][16];  // Wf0    [c][j] padded
    __shared__ __align__(16) float sWi[INITD][HID];
    __shared__ __align__(16) float sWl[HID][OUTD];
    __shared__ float sB0[16], sB1[16], sB2[16], sC[16], sQ[OUTD], sBl[OUTD];
    __shared__ float sDt[TT - 1];

    const int tid = threadIdx.x;

    // ---- zero padded arrays ----
    for (int i = tid; i < 16 * 16; i += NTHR) {
        (&sT1[0][0])[i] = 0.f; (&sT2[0][0])[i] = 0.f; (&sMt[0][0])[i] = 0.f;
    }
    for (int i = tid; i < 8 * 16; i += NTHR)  (&sPt[0][0])[i]  = 0.f;
    for (int i = tid; i < 32 * 16; i += NTHR) (&sWf0[0][0])[i] = 0.f;
    if (tid < 16) { sB0[tid] = 0.f; sB1[tid] = 0.f; sB2[tid] = 0.f; sC[tid] = 0.f; }
    __syncthreads();

    // ---- fill transposed weights + fused operators ----
    for (int i = tid; i < HH * HH; i += NTHR) {       // Wf1/Wf2 [15][15]
        int k = i / HH, j = i % HH;
        sT1[j][k] = Wf1[i];
        sT2[j][k] = Wf2[i];
    }
    for (int i = tid; i < HID * HH; i += NTHR) {      // Wf0 [32][15]
        int c = i / HH, j = i % HH;
        sWf0[c][j] = Wf0[i];
    }
    for (int i = tid; i < INITD * HID; i += NTHR) (&sWi[0][0])[i] = Wi[i];
    for (int i = tid; i < HID * OUTD; i += NTHR)  (&sWl[0][0])[i] = Wl[i];

    // M = Wf3 @ Wf0 : M[k][j] = sum_m Wf3[k][m]*Wf0[m][j]   (stored transposed)
    for (int i = tid; i < HH * HH; i += NTHR) {
        int k = i / HH, j = i % HH;
        float acc = 0.f;
#pragma unroll
        for (int m = 0; m < HID; m++) acc = fmaf(Wf3[k * HID + m], Wf0[m * HH + j], acc);
        sMt[j][k] = acc;
    }
    // P = Wf3 @ Wl : P[k][o] = sum_m Wf3[k][m]*Wl[m][o]     (stored transposed)
    for (int i = tid; i < HH * OUTD; i += NTHR) {
        int k = i / OUTD, o = i % OUTD;
        float acc = 0.f;
#pragma unroll
        for (int m = 0; m < HID; m++) acc = fmaf(Wf3[k * HID + m], Wl[m * OUTD + o], acc);
        sPt[o][k] = acc;
    }
    // c = bf3 @ Wf0, q = bf3 @ Wl
    if (tid < HH) {
        float acc = 0.f;
#pragma unroll
        for (int m = 0; m < HID; m++) acc = fmaf(bf3[m], Wf0[m * HH + tid], acc);
        sC[tid] = acc;
    }
    if (tid < OUTD) {
        float acc = 0.f;
#pragma unroll
        for (int m = 0; m < HID; m++) acc = fmaf(bf3[m], Wl[m * OUTD + tid], acc);
        sQ[tid] = acc;
        sBl[tid] = bl[tid];
    }
    if (tid < HH) { sB0[tid] = bf0[tid]; sB1[tid] = bf1[tid]; sB2[tid] = bf2[tid]; }
    for (int t = tid; t < TT - 1; t += NTHR) sDt[t] = times[t + 1] - times[t];
    __syncthreads();

    // ---- mapping: 8 consecutive lanes = one batch element; role r in 0..7 ----
    const int e = blockIdx.x * EPB + (tid >> 3);
    const int r = tid & 7;
    const unsigned FULL = 0xffffffffu;

    // ---- hoist this role's weights into registers (packed k-pairs) ----
    u64 w1e[8], w1o[8], w2e[8], w2o[8], wMe[8], wMo[8], wP[8];
#pragma unroll
    for (int p = 0; p < 8; p++) {
        w1e[p] = *(const u64*)&sT1[2 * r][2 * p];
        w1o[p] = *(const u64*)&sT1[2 * r + 1][2 * p];
        w2e[p] = *(const u64*)&sT2[2 * r][2 * p];
        w2o[p] = *(const u64*)&sT2[2 * r + 1][2 * p];
        wMe[p] = *(const u64*)&sMt[2 * r][2 * p];
        wMo[p] = *(const u64*)&sMt[2 * r + 1][2 * p];
        wP[p]  = *(const u64*)&sPt[r][2 * p];
    }
    const float b1e = sB1[2 * r], b1o = sB1[2 * r + 1];
    const float b2e = sB2[2 * r], b2o = sB2[2 * r + 1];
    const float cE  = sC[2 * r],  cO  = sC[2 * r + 1];
    const float qr  = sQ[r];

    // ---- initial state: h0 = initial@Wi + bi (temporary), then
    //      u0 pair = (h0@Wf0 + bf0)[2r,2r+1],  y0 = (h0@Wl + bl)[r] ----
    u64 up;       // packed {u[2r], u[2r+1]}
    float yr;     // y[r]
    {
        float x[INITD];
#pragma unroll
        for (int k = 0; k < INITD; k++) x[k] = initial[e * INITD + k];
        float h0[HID];
#pragma unroll
        for (int c = 0; c < HID; c++) {
            float a = bi[c];
#pragma unroll
            for (int k = 0; k < INITD; k++) a = fmaf(x[k], sWi[k][c], a);
            h0[c] = a;
        }
        float ua = sB0[2 * r], ub = sB0[2 * r + 1];
        float y  = sBl[r];
#pragma unroll
        for (int c = 0; c < HID; c++) {
            ua = fmaf(h0[c], sWf0[c][2 * r],     ua);
            ub = fmaf(h0[c], sWf0[c][2 * r + 1], ub);
            y  = fmaf(h0[c], sWl[c][r],          y);
        }
        up = pack2(ua, ub);
        yr = y;
    }

    float* __restrict__ oute = out + (size_t)e * TT * OUTD;
    oute[r] = yr;

    u64 zp[8];
    for (int t = 0; t < TT - 1; t++) {
        const float dt = sDt[t];
        const u64 dt2 = pack2(dt, dt);

        // z0 = tanh(u)  (u pair is local; gather full z0)
        float2 uu = unpack2(up);
        u64 pl = pack2(ftanh(uu.x), ftanh(uu.y));
#pragma unroll
        for (int j = 0; j < 8; j++) zp[j] = __shfl_sync(FULL, pl, j, 8);

        // z1 = tanh(z0 @ Wf1 + b1)
        float a0 = ftanh(dot16r(w1e, zp, b1e));
        float a1 = ftanh(dot16r(w1o, zp, b1o));
        pl = pack2(a0, a1);
#pragma unroll
        for (int j = 0; j < 8; j++) zp[j] = __shfl_sync(FULL, pl, j, 8);

        // z2 = tanh(z1 @ Wf2 + b2)
        a0 = ftanh(dot16r(w2e, zp, b2e));
        a1 = ftanh(dot16r(w2o, zp, b2o));
        pl = pack2(a0, a1);
#pragma unroll
        for (int j = 0; j < 8; j++) zp[j] = __shfl_sync(FULL, pl, j, 8);

        // u += dt * (z2 @ M + c)   -- local pair only, no gather
        float d0 = dot16r(wMe, zp, cE);
        float d1 = dot16r(wMo, zp, cO);
        up = fma2(pack2(d0, d1), dt2, up);

        // y += dt * (z2 @ P + q)   -- local scalar, write out
        float dy = dot16r(wP, zp, qr);
        yr = fmaf(dt, dy, yr);
        oute[(size_t)(t + 1) * OUTD + r] = yr;
    }
}

extern "C" void kernel_launch(void* const* d_in, const int* in_sizes, int n_in,
                              void* d_out, int out_size) {
    const float* times   = (const float*)d_in[0];
    const float* initial = (const float*)d_in[1];
    const float* Wi  = (const float*)d_in[2];
    const float* bi  = (const float*)d_in[3];
    const float* Wf0 = (const float*)d_in[4];
    const float* bf0 = (const float*)d_in[5];
    const float* Wf1 = (const float*)d_in[6];
    const float* bf1 = (const float*)d_in[7];
    const float* Wf2 = (const float*)d_in[8];
    const float* bf2 = (const float*)d_in[9];
    const float* Wf3 = (const float*)d_in[10];
    const float* bf3 = (const float*)d_in[11];
    const float* Wl  = (const float*)d_in[12];
    const float* bl  = (const float*)d_in[13];
    float* out = (float*)d_out;

    node_kernel<<<NBLK, NTHR>>>(times, initial, Wi, bi,
                                Wf0, bf0, Wf1, bf1, Wf2, bf2, Wf3, bf3,
                                Wl, bl, out);
}